// round 15
// baseline (speedup 1.0000x reference)
#include <cuda_runtime.h>

// RALoss fused: loss = sum_i mean_j 10*exp(-sum_{hw}(amax[i,j,hw]-aorg[i,j,hw]))
// Shapes: (4, 64, 512, 512) fp32 x2, scalar fp32 out.
// 512 CTAs x 512 threads (2 pair-aligned blocks per pair, single wave,
// 48 warps/SM): halves per-CTA epilogue tax vs the 1024-CTA champion.
// 8 front-batched LDG.128 (L2::256B), acq_rel last-block finalize,
// fixed-order sums -> deterministic.

#define L_DIM 4
#define B_DIM 64
#define PAIRS (L_DIM * B_DIM)        // 256
#define HW (512 * 512)               // 262144 elems per (i,j) map
#define PAIR_F4 (HW / 4)             // 65536 float4 per pair
#define BLKS_PER_PAIR 2
#define THREADS 512
#define NWARPS (THREADS / 32)        // 16
#define ITERS 16                     // per iter: 512 thr * 4 f4 = 2048 f4; 16*2048 = 32768 = PAIR_F4/2
#define GRID_TOTAL (PAIRS * BLKS_PER_PAIR)   // 512 blocks, single wave @4/SM cap

__device__ float g_partials[GRID_TOTAL];
__device__ unsigned int g_done_count;   // zero-init at load; reset each replay

// 128-bit non-coherent load, 256B L2 fetch granularity.
__device__ __forceinline__ float4 ldg_nc_256(const float4* p) {
    float4 v;
    asm("ld.global.nc.L2::256B.v4.f32 {%0,%1,%2,%3}, [%4];"
        : "=f"(v.x), "=f"(v.y), "=f"(v.z), "=f"(v.w)
        : "l"(p));
    return v;
}

__global__ __launch_bounds__(THREADS, 3)
void raloss_fused_kernel(const float4* __restrict__ amax,
                         const float4* __restrict__ aorg,
                         float* __restrict__ out) {
    const unsigned int blk  = blockIdx.x;   // 0..1   (half within pair)
    const unsigned int pair = blockIdx.y;   // 0..255
    const unsigned int tid  = threadIdx.x;
    const unsigned int warp = tid >> 5;
    const unsigned int lane = tid & 31;

    const unsigned int base = pair * PAIR_F4 + blk * (ITERS * THREADS * 4);
    const float4* pa = amax + base + tid;
    const float4* po = aorg + base + tid;

    float acc0 = 0.0f, acc1 = 0.0f, acc2 = 0.0f, acc3 = 0.0f;

#pragma unroll
    for (int it = 0; it < ITERS; it++) {
        float4 ma0 = ldg_nc_256(pa + 0 * THREADS);
        float4 ma1 = ldg_nc_256(pa + 1 * THREADS);
        float4 ma2 = ldg_nc_256(pa + 2 * THREADS);
        float4 ma3 = ldg_nc_256(pa + 3 * THREADS);
        float4 mo0 = ldg_nc_256(po + 0 * THREADS);
        float4 mo1 = ldg_nc_256(po + 1 * THREADS);
        float4 mo2 = ldg_nc_256(po + 2 * THREADS);
        float4 mo3 = ldg_nc_256(po + 3 * THREADS);

        acc0 += (ma0.x - mo0.x) + (ma0.y - mo0.y) + (ma0.z - mo0.z) + (ma0.w - mo0.w);
        acc1 += (ma1.x - mo1.x) + (ma1.y - mo1.y) + (ma1.z - mo1.z) + (ma1.w - mo1.w);
        acc2 += (ma2.x - mo2.x) + (ma2.y - mo2.y) + (ma2.z - mo2.z) + (ma2.w - mo2.w);
        acc3 += (ma3.x - mo3.x) + (ma3.y - mo3.y) + (ma3.z - mo3.z) + (ma3.w - mo3.w);

        pa += 4 * THREADS;
        po += 4 * THREADS;
    }

    float s = (acc0 + acc1) + (acc2 + acc3);

#pragma unroll
    for (int off = 16; off > 0; off >>= 1)
        s += __shfl_xor_sync(0xFFFFFFFFu, s, off);

    __shared__ float warp_sums[NWARPS];
    __shared__ bool  s_is_last;
    if (lane == 0) warp_sums[warp] = s;
    __syncthreads();

    if (warp == 0) {
        float v = (lane < NWARPS) ? warp_sums[lane] : 0.0f;
#pragma unroll
        for (int off = 8; off > 0; off >>= 1)
            v += __shfl_xor_sync(0xFFFFFFFFu, v, off);
        if (lane == 0) {
            g_partials[pair * BLKS_PER_PAIR + blk] = v;
            // Release publishes the partial; winner's acquire sees all partials.
            unsigned int old;
            asm volatile("atom.acq_rel.gpu.global.add.u32 %0, [%1], %2;"
                         : "=r"(old)
                         : "l"(&g_done_count), "r"(1u)
                         : "memory");
            s_is_last = (old == (unsigned int)(GRID_TOTAL - 1));
        }
    }
    __syncthreads();

    // ---- Last block finalizes: 512 partials, L2-resident ----
    if (s_is_last) {
        // Thread t (t < 256) owns pair t: fixed-order sum of its 2 partials.
        float v = 0.0f;
        if (tid < PAIRS) {
            float d = 0.0f;
#pragma unroll
            for (int k = 0; k < BLKS_PER_PAIR; k++)
                d += __ldcg(&g_partials[tid * BLKS_PER_PAIR + k]);
            // contribution: 10*exp(-d)/64  (sum_i mean_j == sum all pairs / 64)
            v = 10.0f * expf(-d) * (1.0f / (float)B_DIM);
        }

#pragma unroll
        for (int off = 16; off > 0; off >>= 1)
            v += __shfl_xor_sync(0xFFFFFFFFu, v, off);

        if (lane == 0) warp_sums[warp] = v;
        __syncthreads();

        if (warp == 0) {
            float w = (lane < NWARPS) ? warp_sums[lane] : 0.0f;
#pragma unroll
            for (int off = 8; off > 0; off >>= 1)
                w += __shfl_xor_sync(0xFFFFFFFFu, w, off);
            if (lane == 0) {
                out[0] = w;
                g_done_count = 0;   // reset for next graph replay
            }
        }
    }
}

extern "C" void kernel_launch(void* const* d_in, const int* in_sizes, int n_in,
                              void* d_out, int out_size) {
    const float4* amax = (const float4*)d_in[0];
    const float4* aorg = (const float4*)d_in[1];
    float* out = (float*)d_out;

    dim3 grid(BLKS_PER_PAIR, PAIRS, 1);
    raloss_fused_kernel<<<grid, THREADS>>>(amax, aorg, out);
}

// round 16
// speedup vs baseline: 1.0994x; 1.0994x over previous
#include <cuda_runtime.h>

// RALoss split: loss = sum_i mean_j 10*exp(-sum_{hw}(amax[i,j,hw]-aorg[i,j,hw]))
// Shapes: (4, 64, 512, 512) fp32 x2, scalar fp32 out.
// Kernel 1: champion streaming (1024 pair-aligned blocks, single wave,
//   8 front-batched LDG.128 L2::256B) with ZERO sync machinery — block
//   reduce + one STG of the partial. No fence, no atomic, no tail.
// Kernel 2: 1-block finalize (fixed-order sums -> deterministic). The
//   kernel boundary orders the partial writes; under graph-replay timing
//   this 1-block kernel overlaps the next replay's streaming (R2 evidence:
//   split 86.2 vs fused 86.8 on the 16384-block config).

#define L_DIM 4
#define B_DIM 64
#define PAIRS (L_DIM * B_DIM)        // 256
#define HW (512 * 512)               // 262144 elems per (i,j) map
#define PAIR_F4 (HW / 4)             // 65536 float4 per pair
#define BLKS_PER_PAIR 4
#define THREADS 256
#define ITERS 16                     // per iter: 256 thr * 4 f4 = 1024 f4
#define GRID_TOTAL (PAIRS * BLKS_PER_PAIR)   // 1024 blocks, single wave

__device__ float g_partials[GRID_TOTAL];

// 128-bit non-coherent load, 256B L2 fetch granularity.
__device__ __forceinline__ float4 ldg_nc_256(const float4* p) {
    float4 v;
    asm("ld.global.nc.L2::256B.v4.f32 {%0,%1,%2,%3}, [%4];"
        : "=f"(v.x), "=f"(v.y), "=f"(v.z), "=f"(v.w)
        : "l"(p));
    return v;
}

__global__ __launch_bounds__(THREADS, 7)
void raloss_reduce_kernel(const float4* __restrict__ amax,
                          const float4* __restrict__ aorg) {
    const unsigned int blk  = blockIdx.x;   // 0..3   (chunk within pair)
    const unsigned int pair = blockIdx.y;   // 0..255
    const unsigned int tid  = threadIdx.x;
    const unsigned int warp = tid >> 5;
    const unsigned int lane = tid & 31;

    const unsigned int base = pair * PAIR_F4 + blk * (ITERS * THREADS * 4);
    const float4* pa = amax + base + tid;
    const float4* po = aorg + base + tid;

    float acc0 = 0.0f, acc1 = 0.0f, acc2 = 0.0f, acc3 = 0.0f;

#pragma unroll
    for (int it = 0; it < ITERS; it++) {
        float4 ma0 = ldg_nc_256(pa + 0 * THREADS);
        float4 ma1 = ldg_nc_256(pa + 1 * THREADS);
        float4 ma2 = ldg_nc_256(pa + 2 * THREADS);
        float4 ma3 = ldg_nc_256(pa + 3 * THREADS);
        float4 mo0 = ldg_nc_256(po + 0 * THREADS);
        float4 mo1 = ldg_nc_256(po + 1 * THREADS);
        float4 mo2 = ldg_nc_256(po + 2 * THREADS);
        float4 mo3 = ldg_nc_256(po + 3 * THREADS);

        acc0 += (ma0.x - mo0.x) + (ma0.y - mo0.y) + (ma0.z - mo0.z) + (ma0.w - mo0.w);
        acc1 += (ma1.x - mo1.x) + (ma1.y - mo1.y) + (ma1.z - mo1.z) + (ma1.w - mo1.w);
        acc2 += (ma2.x - mo2.x) + (ma2.y - mo2.y) + (ma2.z - mo2.z) + (ma2.w - mo2.w);
        acc3 += (ma3.x - mo3.x) + (ma3.y - mo3.y) + (ma3.z - mo3.z) + (ma3.w - mo3.w);

        pa += 4 * THREADS;
        po += 4 * THREADS;
    }

    float s = (acc0 + acc1) + (acc2 + acc3);

#pragma unroll
    for (int off = 16; off > 0; off >>= 1)
        s += __shfl_xor_sync(0xFFFFFFFFu, s, off);

    __shared__ float warp_sums[THREADS / 32];
    if (lane == 0) warp_sums[warp] = s;
    __syncthreads();

    if (warp == 0) {
        float v = (lane < (THREADS / 32)) ? warp_sums[lane] : 0.0f;
#pragma unroll
        for (int off = 4; off > 0; off >>= 1)
            v += __shfl_xor_sync(0xFFFFFFFFu, v, off);
        if (lane == 0)
            g_partials[pair * BLKS_PER_PAIR + blk] = v;
    }
    // Done. No fence, no atomic, no tail — kernel boundary publishes partials.
}

__global__ __launch_bounds__(PAIRS)
void raloss_finalize_kernel(float* __restrict__ out) {
    const int t = threadIdx.x;   // thread t owns pair t (256 threads)
    const int warp = t >> 5;
    const int lane = t & 31;

    // Fixed-order sum of pair t's 4 partials -> deterministic.
    float d = 0.0f;
#pragma unroll
    for (int k = 0; k < BLKS_PER_PAIR; k++)
        d += g_partials[t * BLKS_PER_PAIR + k];

    // contribution: 10*exp(-d)/64  (sum_i mean_j == sum over 256 pairs / 64)
    float v = 10.0f * expf(-d) * (1.0f / (float)B_DIM);

#pragma unroll
    for (int off = 16; off > 0; off >>= 1)
        v += __shfl_xor_sync(0xFFFFFFFFu, v, off);

    __shared__ float warp_sums[PAIRS / 32];
    if (lane == 0) warp_sums[warp] = v;
    __syncthreads();

    if (warp == 0) {
        float w = (lane < (PAIRS / 32)) ? warp_sums[lane] : 0.0f;
#pragma unroll
        for (int off = 4; off > 0; off >>= 1)
            w += __shfl_xor_sync(0xFFFFFFFFu, w, off);
        if (lane == 0)
            out[0] = w;
    }
}

extern "C" void kernel_launch(void* const* d_in, const int* in_sizes, int n_in,
                              void* d_out, int out_size) {
    const float4* amax = (const float4*)d_in[0];
    const float4* aorg = (const float4*)d_in[1];
    float* out = (float*)d_out;

    dim3 grid(BLKS_PER_PAIR, PAIRS, 1);
    raloss_reduce_kernel<<<grid, THREADS>>>(amax, aorg);
    raloss_finalize_kernel<<<1, PAIRS>>>(out);
}